// round 17
// baseline (speedup 1.0000x reference)
#include <cuda_runtime.h>
#include <math.h>

#define DIMD 128
#define PMAX 3136
#define PIVW 144   // 128 floats + 4-float pad per 32-float group (bank stagger)

typedef unsigned long long ull;

// Scratch: RECIPROCAL of diag(inv(b_covs[p]))[d], stored [D][P].
__device__ float g_rdinv[DIMD * PMAX];

// ---- packed f32x2 helpers (Blackwell sm_103a) ------------------------------
__device__ __forceinline__ ull pack2(float lo, float hi) {
    ull r; asm("mov.b64 %0, {%1, %2};" : "=l"(r) : "f"(lo), "f"(hi)); return r;
}
__device__ __forceinline__ float2 unpack2(ull v) {
    float2 r; asm("mov.b64 {%0, %1}, %2;" : "=f"(r.x), "=f"(r.y) : "l"(v)); return r;
}
__device__ __forceinline__ ull fma2(ull a, ull b, ull c) {
    ull d; asm("fma.rn.f32x2 %0, %1, %2, %3;" : "=l"(d) : "l"(a), "l"(b), "l"(c)); return d;
}
__device__ __forceinline__ ull mul2(ull a, ull b) {
    ull d; asm("mul.rn.f32x2 %0, %1, %2;" : "=l"(d) : "l"(a), "l"(b)); return d;
}
// Fast reciprocal: rcp.approx + 1 Newton step (fp32-accurate).
__device__ __forceinline__ float frcp(float x) {
    float r; asm("rcp.approx.ftz.f32 %0, %1;" : "=f"(r) : "f"(x));
    return r * fmaf(-x, r, 2.0f);
}

// ---------------------------------------------------------------------------
// Phase A: packed-f32x2 Gauss-Jordan (R16 base = 433us phase A) with the
// pivot COLUMN staged as DUPLICATED (v,v) ull pairs. The 16 pack2 MOVs per
// thread per step (R16 profile: alu pipe 44% co-dominant with fma 54%) are
// eliminated; ci2 now comes straight from 4x LDS.128 broadcasts (2 distinct
// addresses per warp -> conflict-free). Packing happens only on the 16
// column-staging threads. Differences from the failed R14 attempt: pivbuf
// keeps the R16 bank-stagger padding, and the pivot scalar is a plain C++
// float load of the pair's low half (LDS.32 broadcast, no generic address).
// ---------------------------------------------------------------------------
template<int KQ>
__device__ __forceinline__ void gj_step(
    ull (&Tp)[8][4],
    ull (&colD)[2][DIMD], float (&pivbuf)[2][PIVW],
    int kk, int ty, int tx, int R0, int C0, int CP)
{
    constexpr int BUF  = KQ & 1;
    constexpr int NBUF = BUF ^ 1;
    const int k = (kk << 3) + KQ;

    // Pivot scalar: low half of the duplicated pair (LDS.32 broadcast).
    float ck = *reinterpret_cast<const float*>(&colD[BUF][k]);
    float pv  = frcp(ck);
    float npv = -pv;
    ull npv2  = pack2(npv, npv);

    // Pivot column, pre-duplicated pairs: 4x LDS.128 broadcast, zero MOVs.
    ull ci2[8];
    {
        const ulonglong2* c4 = reinterpret_cast<const ulonglong2*>(&colD[BUF][R0]);
        ulonglong2 u0 = c4[0], u1 = c4[1], u2 = c4[2], u3 = c4[3];
        ci2[0]=u0.x; ci2[1]=u0.y; ci2[2]=u1.x; ci2[3]=u1.y;
        ci2[4]=u2.x; ci2[5]=u2.y; ci2[6]=u3.x; ci2[7]=u3.y;
    }

    // Pivot row (raw, bank-staggered), packed adjacent pairs.
    ull rj2[4];
    {
        const ulonglong2* r4 = reinterpret_cast<const ulonglong2*>(&pivbuf[BUF][CP]);
        ulonglong2 u0 = r4[0], u1 = r4[1];
        rj2[0]=u0.x; rj2[1]=u0.y; rj2[2]=u1.x; rj2[3]=u1.y;
    }
    ull sn2[4];                       // -(row_k * pv)
#pragma unroll
    for (int b = 0; b < 4; b++) sn2[b] = mul2(rj2[b], npv2);

    // Rank-1 update: 32 packed FMAs.
#pragma unroll
    for (int a = 0; a < 8; a++)
#pragma unroll
        for (int b = 0; b < 4; b++)
            Tp[a][b] = fma2(ci2[a], sn2[b], Tp[a][b]);

    // Pivot-row fixup: M[k][j] = row_k[j] * pv.
    if (kk == ty) {
        ull pv2 = pack2(pv, pv);
#pragma unroll
        for (int b = 0; b < 4; b++) Tp[KQ][b] = mul2(rj2[b], pv2);
    }
    // Pivot-col fixup: M[i][k] = -ci[i]*pv; M[k][k] = pv. (After row fixup.)
    if (kk == tx) {
        constexpr int PB = KQ >> 1;
#pragma unroll
        for (int a = 0; a < 8; a++) {
            float cia = unpack2(ci2[a]).x;
            float2 h = unpack2(Tp[a][PB]);
            float v = (R0 + a == k) ? pv : cia * npv;
            if (KQ & 1) h.y = v; else h.x = v;
            Tp[a][PB] = pack2(h.x, h.y);
        }
    }

    // Stage next pivot column/row from the UPDATED matrix.
    if (k + 1 < DIMD) {
        constexpr int KNQ = (KQ + 1) & 7;
        constexpr int PBN = KNQ >> 1;
        const int kkn = kk + ((KQ + 1) >> 3);
        if (kkn == tx) {
            // 16 staging threads pay the packing (8 pack2 each).
#pragma unroll
            for (int a = 0; a < 8; a++) {
                float2 h = unpack2(Tp[a][PBN]);
                float v = (KNQ & 1) ? h.y : h.x;
                colD[NBUF][R0 + a] = pack2(v, v);
            }
        }
        if (kkn == ty) {
            ulonglong2* d4 = reinterpret_cast<ulonglong2*>(&pivbuf[NBUF][CP]);
            d4[0] = make_ulonglong2(Tp[KNQ][0], Tp[KNQ][1]);
            d4[1] = make_ulonglong2(Tp[KNQ][2], Tp[KNQ][3]);
        }
    }
    __syncthreads();
}

__global__ __launch_bounds__(256, 2)
void inv_diag_kernel(const float* __restrict__ covs, int P)
{
    int p = blockIdx.x;
    const float* A = covs + (size_t)p * DIMD * DIMD;

    int tid = threadIdx.x;
    int ty = tid >> 4;
    int tx = tid & 15;
    int R0 = ty << 3;
    int C0 = tx << 3;
    int CP = C0 + ((C0 >> 5) << 2);   // bank-staggered pivbuf base

    ull Tp[8][4];     // 8 rows x 4 packed col-pairs = 8x8 fp32 tile
#pragma unroll
    for (int a = 0; a < 8; a++) {
        const ulonglong2* src =
            reinterpret_cast<const ulonglong2*>(A + (size_t)(R0 + a) * DIMD + C0);
        ulonglong2 v0 = src[0], v1 = src[1];
        Tp[a][0]=v0.x; Tp[a][1]=v0.y; Tp[a][2]=v1.x; Tp[a][3]=v1.y;
    }

    __shared__ __align__(16) ull   colD[2][DIMD];     // pivot column, (v,v) pairs
    __shared__ __align__(16) float pivbuf[2][PIVW];   // raw pivot row (padded)

    // Stage step 0.
    if (tx == 0) {
#pragma unroll
        for (int a = 0; a < 8; a++) {
            float v = unpack2(Tp[a][0]).x;
            colD[0][R0 + a] = pack2(v, v);
        }
    }
    if (ty == 0) {
        ulonglong2* d4 = reinterpret_cast<ulonglong2*>(&pivbuf[0][CP]);
        d4[0] = make_ulonglong2(Tp[0][0], Tp[0][1]);
        d4[1] = make_ulonglong2(Tp[0][2], Tp[0][3]);
    }
    __syncthreads();

#pragma unroll 1
    for (int kk = 0; kk < 16; kk++) {
        gj_step<0>(Tp, colD, pivbuf, kk, ty, tx, R0, C0, CP);
        gj_step<1>(Tp, colD, pivbuf, kk, ty, tx, R0, C0, CP);
        gj_step<2>(Tp, colD, pivbuf, kk, ty, tx, R0, C0, CP);
        gj_step<3>(Tp, colD, pivbuf, kk, ty, tx, R0, C0, CP);
        gj_step<4>(Tp, colD, pivbuf, kk, ty, tx, R0, C0, CP);
        gj_step<5>(Tp, colD, pivbuf, kk, ty, tx, R0, C0, CP);
        gj_step<6>(Tp, colD, pivbuf, kk, ty, tx, R0, C0, CP);
        gj_step<7>(Tp, colD, pivbuf, kk, ty, tx, R0, C0, CP);
    }

    // Registers now hold inv(A). Emit reciprocal of its diagonal.
    if (ty == tx) {
#pragma unroll
        for (int a = 0; a < 8; a++) {
            float2 h = unpack2(Tp[a][a >> 1]);
            float dv = (a & 1) ? h.y : h.x;
            g_rdinv[(size_t)(R0 + a) * P + p] = frcp(dv);
        }
    }
}

// ncu alignment: 3 launches per kernel_launch call => the profiled launch
// (index 3 of the timed sequence) is call 2's inv_diag_kernel.
__global__ void nop_pad_kernel() {}

// ---------------------------------------------------------------------------
// Phase B: streaming whitening + cosine similarity, coalesced:
// block = 256 threads = 64 outputs x 4 d-quarters; a warp's 32 lanes read 32
// consecutive p => full 128B transactions. Cross-quarter reduction via smem.
// ---------------------------------------------------------------------------
__global__ void ace_kernel(const float* __restrict__ X,
                           const float* __restrict__ bmean,
                           const float* __restrict__ covs,
                           const float* __restrict__ sig,
                           const int* __restrict__ covtype,
                           float* __restrict__ out,
                           int B, int P)
{
    int t    = threadIdx.x;
    int sub  = t >> 6;
    int slot = t & 63;
    int idx  = blockIdx.x * 64 + slot;
    bool valid = idx < B * P;
    int b = valid ? idx / P : 0;
    int p = valid ? idx - b * P : 0;
    int ct = *covtype;

    float ww = 0.f, ws = 0.f, ss = 0.f;

    if (valid) {
        if (ct == 0) {
            for (int m = sub * 32; m < sub * 32 + 32; m++) {
                float w = 0.f;
                const float* cr = covs + ((size_t)p * DIMD + m) * DIMD;
                for (int d = 0; d < DIMD; d++) {
                    float xc = X[((size_t)b * DIMD + d) * P + p] - bmean[(size_t)d * P + p];
                    w = fmaf(xc, cr[d], w);
                }
                float s = sig[(size_t)m * P + p];
                ww = fmaf(w, w, ww);
                ws = fmaf(w, s, ws);
                ss = fmaf(s, s, ss);
            }
        } else {
            bool use_diag = (ct == 1);
            int d0 = sub * 32;
#pragma unroll 16
            for (int i = 0; i < 32; i++) {
                int d = d0 + i;
                float xc = X[((size_t)b * DIMD + d) * P + p] - bmean[(size_t)d * P + p];
                float s  = sig[(size_t)d * P + p];
                float w  = use_diag ? (xc * g_rdinv[(size_t)d * P + p]) : xc;
                ww = fmaf(w, w, ww);
                ws = fmaf(w, s, ws);
                ss = fmaf(s, s, ss);
            }
        }
    }

    __shared__ float sred[3][4][64];
    sred[0][sub][slot] = ww;
    sred[1][sub][slot] = ws;
    sred[2][sub][slot] = ss;
    __syncthreads();

    if (sub == 0 && valid) {
        float tw = 0.f, ts = 0.f, tq = 0.f;
#pragma unroll
        for (int q = 0; q < 4; q++) {
            tw += sred[0][q][slot];
            ts += sred[1][q][slot];
            tq += sred[2][q][slot];
        }
        float denom = fmaxf(sqrtf(tw), 1e-12f) * fmaxf(sqrtf(tq), 1e-12f);
        out[idx] = ts / denom;
    }
}

extern "C" void kernel_launch(void* const* d_in, const int* in_sizes, int n_in,
                              void* d_out, int out_size)
{
    const float* X      = (const float*)d_in[0];
    const float* bmean  = (const float*)d_in[1];
    const float* covs   = (const float*)d_in[2];
    const float* sig    = (const float*)d_in[3];
    const int*   ctype  = (const int*)d_in[4];
    float*       out    = (float*)d_out;

    int P = in_sizes[2] / (DIMD * DIMD);           // 3136
    int B = in_sizes[0] / (DIMD * P);              // 32

    inv_diag_kernel<<<P, 256>>>(covs, P);

    int total = B * P;
    ace_kernel<<<(total + 63) / 64, 256>>>(X, bmean, covs, sig, ctype, out, B, P);

    nop_pad_kernel<<<1, 32>>>();   // keep ncu aimed at inv_diag_kernel
}